// round 1
// baseline (speedup 1.0000x reference)
#include <cuda_runtime.h>

// Bilateral filter 5x5, sigma_color = sigma_space = 1.1, reflect padding.
// Input/output: (16, 3, 512, 512) float32.
//
// Key identity: both the color-weight normalization (per-window) and the
// space-kernel normalization (global) are scalar factors that cancel in
// num/den, so:
//   out = sum_{k} exp(-diff^2 * a) * exp(-r2_k * a) * p_k
//       / sum_{k} exp(-diff^2 * a) * exp(-r2_k * a)
// with a = 1/(2*1.1^2) = 0.413223140495868.
//
// exp(-a*u) for u = diff^2 in [0,1) is replaced by a degree-3 Taylor
// polynomial centered at u=0.5 (abs err <= ~7e-5, rel err on weights
// <= 1.1e-4, output error ~1e-4 << 1e-3 gate).

#define H 512
#define W 512
#define NPLANES 48         // B*C = 16*3

#define TILE_W 32
#define TILE_H 8
#define SM_W   36          // TILE_W + 4
#define SM_H   12          // TILE_H + 4

// Spatial 1D gaussian (unnormalized): exp(-a*d^2), d in {-2..2}
#define G2 0.19149516f
#define G1 0.66151464f
#define G0 1.0f

// Poly coefficients for exp(-a*u), u in [0,1], centered Taylor deg 3 @ u=0.5
#define PC0  0.99993560f
#define PC1 -0.41270252f
#define PC2  0.08378699f
#define PC3 -0.00956474f

__device__ __forceinline__ int reflect_idx(int i, int n) {
    // single-reflection is enough for pad=2
    if (i < 0)  i = -i;
    if (i >= n) i = 2 * n - 2 - i;
    return i;
}

__global__ __launch_bounds__(TILE_W * TILE_H)
void bilateral_kernel(const float* __restrict__ in, float* __restrict__ out) {
    __shared__ float sm[SM_H][SM_W];

    const int tx = threadIdx.x;
    const int ty = threadIdx.y;
    const int bx = blockIdx.x * TILE_W;
    const int by = blockIdx.y * TILE_H;
    const int plane = blockIdx.z;
    const long pbase = (long)plane * (H * W);

    // ---- cooperative tile load with reflect padding ----
    const int t = ty * TILE_W + tx;   // 0..255
    #pragma unroll
    for (int idx = 0; idx < SM_H * SM_W; idx += TILE_W * TILE_H) {
        int i = idx + t;
        if (i < SM_H * SM_W) {
            int r = i / SM_W;
            int c = i - r * SM_W;
            int gy = reflect_idx(by - 2 + r, H);
            int gx = reflect_idx(bx - 2 + c, W);
            sm[r][c] = in[pbase + gy * W + gx];
        }
    }
    __syncthreads();

    // ---- 25-tap bilateral, fully unrolled ----
    const float ctr = sm[ty + 2][tx + 2];
    float num = 0.0f;
    float den = 0.0f;

    const float g[5] = { G2, G1, G0, G1, G2 };

    #pragma unroll
    for (int ki = 0; ki < 5; ki++) {
        #pragma unroll
        for (int kj = 0; kj < 5; kj++) {
            float p = sm[ty + ki][tx + kj];
            float d = p - ctr;
            float u = d * d;
            // wc ~= exp(-a*u)
            float wc = fmaf(fmaf(fmaf(PC3, u, PC2), u, PC1), u, PC0);
            float s = g[ki] * g[kj];          // compile-time constant
            den = fmaf(wc, s, den);           // FFMA-imm
            num = fmaf(wc, s * p, num);       // s*p: FMUL-imm
        }
    }

    out[pbase + (by + ty) * W + (bx + tx)] = __fdividef(num, den);
}

extern "C" void kernel_launch(void* const* d_in, const int* in_sizes, int n_in,
                              void* d_out, int out_size) {
    const float* x = (const float*)d_in[0];
    float* y = (float*)d_out;
    dim3 block(TILE_W, TILE_H);
    dim3 grid(W / TILE_W, H / TILE_H, NPLANES);
    bilateral_kernel<<<grid, block>>>(x, y);
}

// round 2
// speedup vs baseline: 1.0820x; 1.0820x over previous
#include <cuda_runtime.h>

// Bilateral 5x5, sigma_color = sigma_space = 1.1, reflect pad, (16,3,512,512) f32.
//
// out = sum_k exp(-d^2*a)*exp(-r2_k*a)*p_k / sum_k exp(-d^2*a)*exp(-r2_k*a)
// (both reference normalizations cancel).  exp(-a*u), u in [0,1], replaced by
// a deg-3 poly (abs err ~7e-5; measured end-to-end rel_err 1.1e-5 in R1).
//
// R2: packed f32x2 math — 2 horizontal pixels per thread, per-s-class
// accumulators so the spatial weight leaves the inner loop.

#define H 512
#define W 512
#define NPLANES 48

#define TILE_W 64          // pixels per block in x (2 per thread)
#define TILE_H 8
#define BLK_X 32
#define BLK_Y 8
#define SM_W  68           // TILE_W + 4
#define SM_H  12           // TILE_H + 4

// 1D spatial gaussian (unnormalized) exp(-a*d^2), d in {-2..2}
#define G0 1.0f
#define G1 0.66151464f
#define G2 0.19149516f

// poly coeffs for exp(-a*u), u in [0,1]
#define PC0  0.99993560f
#define PC1 -0.41270252f
#define PC2  0.08378699f
#define PC3 -0.00956474f

typedef unsigned long long u64;

union F2 { u64 q; float f[2]; };

__device__ __forceinline__ u64 pk(float lo, float hi) {
    u64 r; asm("mov.b64 %0, {%1, %2};" : "=l"(r) : "f"(lo), "f"(hi)); return r;
}
__device__ __forceinline__ u64 f2add(u64 a, u64 b) {
    u64 d; asm("add.rn.f32x2 %0, %1, %2;" : "=l"(d) : "l"(a), "l"(b)); return d;
}
__device__ __forceinline__ u64 f2mul(u64 a, u64 b) {
    u64 d; asm("mul.rn.f32x2 %0, %1, %2;" : "=l"(d) : "l"(a), "l"(b)); return d;
}
__device__ __forceinline__ u64 f2fma(u64 a, u64 b, u64 c) {
    u64 d; asm("fma.rn.f32x2 %0, %1, %2, %3;" : "=l"(d) : "l"(a), "l"(b), "l"(c)); return d;
}

__device__ __forceinline__ int reflect_idx(int i, int n) {
    if (i < 0)  i = -i;
    if (i >= n) i = 2 * n - 2 - i;
    return i;
}

__global__ __launch_bounds__(BLK_X * BLK_Y)
void bilateral_kernel(const float* __restrict__ in, float* __restrict__ out) {
    __shared__ __align__(16) float sm[SM_H][SM_W];

    const int tx = threadIdx.x;
    const int ty = threadIdx.y;
    const int bx = blockIdx.x * TILE_W;
    const int by = blockIdx.y * TILE_H;
    const long pbase = (long)blockIdx.z * (H * W);

    // ---- cooperative tile load with reflect padding ----
    const int t = ty * BLK_X + tx;   // 0..255
    #pragma unroll
    for (int idx = 0; idx < SM_H * SM_W; idx += BLK_X * BLK_Y) {
        int i = idx + t;
        if (i < SM_H * SM_W) {
            int r = i / SM_W;
            int c = i - r * SM_W;
            int gy = reflect_idx(by - 2 + r, H);
            int gx = reflect_idx(bx - 2 + c, W);
            sm[r][c] = in[pbase + gy * W + gx];
        }
    }
    __syncthreads();

    // packed poly constants
    const u64 C3 = pk(PC3, PC3);
    const u64 C2 = pk(PC2, PC2);
    const u64 C1 = pk(PC1, PC1);
    const u64 C0 = pk(PC0, PC0);

    const int col = 2 * tx;          // base smem col for this thread's pair

    // center pair (cols col+2, col+3 of row ty+2), negated for the d-add
    F2 ctr; ctr.q = *(const u64*)&sm[ty + 2][col + 2];
    const u64 nctr = pk(-ctr.f[0], -ctr.f[1]);

    // per-s-class accumulators: 0:G0G0 1:G0G1 2:G0G2 3:G1G1 4:G1G2 5:G2G2
    u64 num[6], den[6];
    #pragma unroll
    for (int c = 0; c < 6; c++) { num[c] = 0ull; den[c] = 0ull; }

    static const int cls[5][5] = {
        {5,4,2,4,5},
        {4,3,1,3,4},
        {2,1,0,1,2},
        {4,3,1,3,4},
        {5,4,2,4,5},
    };

    #pragma unroll
    for (int ki = 0; ki < 5; ki++) {
        const float* row = &sm[ty + ki][col];
        F2 r01, r23, r45;
        r01.q = *(const u64*)&row[0];
        r23.q = *(const u64*)&row[2];
        r45.q = *(const u64*)&row[4];

        u64 pj[5];
        pj[0] = r01.q;
        pj[1] = pk(r01.f[1], r23.f[0]);
        pj[2] = r23.q;
        pj[3] = pk(r23.f[1], r45.f[0]);
        pj[4] = r45.q;

        #pragma unroll
        for (int kj = 0; kj < 5; kj++) {
            const int c = cls[ki][kj];
            u64 p = pj[kj];
            u64 d = f2add(p, nctr);
            u64 u = f2mul(d, d);
            u64 w = f2fma(C3, u, C2);
            w = f2fma(w, u, C1);
            w = f2fma(w, u, C0);          // wc ~= exp(-a*d^2)
            den[c] = f2add(den[c], w);
            num[c] = f2fma(w, p, num[c]);
        }
    }

    // ---- apply spatial class weights, divide, store ----
    const float S[6] = { G0*G0, G0*G1, G0*G2, G1*G1, G1*G2, G2*G2 };
    float n0 = 0.f, n1 = 0.f, d0 = 0.f, d1 = 0.f;
    #pragma unroll
    for (int c = 0; c < 6; c++) {
        F2 n, d; n.q = num[c]; d.q = den[c];
        n0 = fmaf(S[c], n.f[0], n0);
        n1 = fmaf(S[c], n.f[1], n1);
        d0 = fmaf(S[c], d.f[0], d0);
        d1 = fmaf(S[c], d.f[1], d1);
    }

    float2 o;
    o.x = __fdividef(n0, d0);
    o.y = __fdividef(n1, d1);
    *(float2*)&out[pbase + (by + ty) * W + bx + col] = o;
}

extern "C" void kernel_launch(void* const* d_in, const int* in_sizes, int n_in,
                              void* d_out, int out_size) {
    const float* x = (const float*)d_in[0];
    float* y = (float*)d_out;
    dim3 block(BLK_X, BLK_Y);
    dim3 grid(W / TILE_W, H / TILE_H, NPLANES);
    bilateral_kernel<<<grid, block>>>(x, y);
}

// round 3
// speedup vs baseline: 1.0889x; 1.0064x over previous
#include <cuda_runtime.h>

// Bilateral 5x5, sigma_color = sigma_space = 1.1, reflect pad, (16,3,512,512) f32.
//
// out = sum_k exp(-d^2*a)*exp(-r2_k*a)*p_k / sum_k exp(-d^2*a)*exp(-r2_k*a)
// (the reference's two normalizations cancel).  exp(-a*u), u in [0,1], is a
// deg-3 centered Taylor poly (measured end-to-end rel_err 1.1e-5).
//
// R3: f32x2 packed math (2 px/thread) + row-factorized spatial weights
// (4 accumulators instead of 12) + shifted smem copy for aligned odd-pair
// LDS.64 (no pack MOVs) + occupancy floor via launch_bounds.

#define H 512
#define W 512
#define NPLANES 48

#define TILE_W 64
#define TILE_H 8
#define BLK_X 32
#define BLK_Y 8
#define SM_W  68           // TILE_W + 4
#define SM_H  12           // TILE_H + 4
#define SM_N  (SM_H * SM_W)

#define G1 0.66151464f
#define G2 0.19149516f

#define PC0  0.99993560f
#define PC1 -0.41270252f
#define PC2  0.08378699f
#define PC3 -0.00956474f

typedef unsigned long long u64;

__device__ __forceinline__ u64 pk(float lo, float hi) {
    u64 r; asm("mov.b64 %0, {%1, %2};" : "=l"(r) : "f"(lo), "f"(hi)); return r;
}
__device__ __forceinline__ u64 f2add(u64 a, u64 b) {
    u64 d; asm("add.rn.f32x2 %0, %1, %2;" : "=l"(d) : "l"(a), "l"(b)); return d;
}
__device__ __forceinline__ u64 f2mul(u64 a, u64 b) {
    u64 d; asm("mul.rn.f32x2 %0, %1, %2;" : "=l"(d) : "l"(a), "l"(b)); return d;
}
__device__ __forceinline__ u64 f2fma(u64 a, u64 b, u64 c) {
    u64 d; asm("fma.rn.f32x2 %0, %1, %2, %3;" : "=l"(d) : "l"(a), "l"(b), "l"(c)); return d;
}
__device__ __forceinline__ void unpk(u64 q, float& lo, float& hi) {
    asm("mov.b64 {%0, %1}, %2;" : "=f"(lo), "=f"(hi) : "l"(q));
}

__device__ __forceinline__ int reflect_idx(int i, int n) {
    if (i < 0)  i = -i;
    if (i >= n) i = 2 * n - 2 - i;
    return i;
}

__global__ __launch_bounds__(BLK_X * BLK_Y, 6)
void bilateral_kernel(const float* __restrict__ in, float* __restrict__ out) {
    // smB[r][c] == smA[r][c+1]  (shifted copy -> odd pairs are 8B-aligned)
    __shared__ __align__(8) float smA[SM_H][SM_W];
    __shared__ __align__(8) float smB[SM_H][SM_W];

    const int tx = threadIdx.x;
    const int ty = threadIdx.y;
    const int bx = blockIdx.x * TILE_W;
    const int by = blockIdx.y * TILE_H;
    const long pbase = (long)blockIdx.z * (H * W);

    // ---- cooperative tile load with reflect padding, dual-store ----
    const int t = ty * BLK_X + tx;
    #pragma unroll
    for (int idx = 0; idx < SM_N; idx += BLK_X * BLK_Y) {
        int i = idx + t;
        if (i < SM_N) {
            int r = i / SM_W;
            int c = i - r * SM_W;
            int gy = reflect_idx(by - 2 + r, H);
            int gx = reflect_idx(bx - 2 + c, W);
            float v = in[pbase + gy * W + gx];
            smA[r][c] = v;
            if (c > 0) smB[r][c - 1] = v;
        }
    }
    __syncthreads();

    const u64 C3 = pk(PC3, PC3);
    const u64 C2 = pk(PC2, PC2);
    const u64 C1 = pk(PC1, PC1);
    const u64 C0 = pk(PC0, PC0);
    const u64 G1p = pk(G1, G1);
    const u64 G2p = pk(G2, G2);

    const int col = 2 * tx;

    float c0, c1;
    unpk(*(const u64*)&smA[ty + 2][col + 2], c0, c1);
    const u64 nctr = pk(-c0, -c1);

    u64 num = 0ull, den = 0ull;

    #pragma unroll
    for (int ki = 0; ki < 5; ki++) {
        const float* rA = &smA[ty + ki][col];
        const float* rB = &smB[ty + ki][col];
        u64 p0 = *(const u64*)(rA + 0);
        u64 p1 = *(const u64*)(rB + 0);
        u64 p2 = *(const u64*)(rA + 2);
        u64 p3 = *(const u64*)(rB + 2);
        u64 p4 = *(const u64*)(rA + 4);

        u64 rnum = 0ull, rden = 0ull;

        // tap macro: w = poly(d^2); optional *g; accumulate
        #define TAP(P, GREG, HASG)                              \
        {                                                       \
            u64 d_ = f2add((P), nctr);                          \
            u64 u_ = f2mul(d_, d_);                             \
            u64 w_ = f2fma(C3, u_, C2);                         \
            w_ = f2fma(w_, u_, C1);                             \
            w_ = f2fma(w_, u_, C0);                             \
            if (HASG) w_ = f2mul(w_, (GREG));                   \
            rden = f2add(rden, w_);                             \
            rnum = f2fma(w_, (P), rnum);                        \
        }

        TAP(p0, G2p, true)
        TAP(p1, G1p, true)
        TAP(p2, G2p, false)
        TAP(p3, G1p, true)
        TAP(p4, G2p, true)
        #undef TAP

        if (ki == 2) {
            den = f2add(den, rden);
            num = f2add(num, rnum);
        } else if (ki == 1 || ki == 3) {
            den = f2fma(G1p, rden, den);
            num = f2fma(G1p, rnum, num);
        } else {
            den = f2fma(G2p, rden, den);
            num = f2fma(G2p, rnum, num);
        }
    }

    float n0, n1, d0, d1;
    unpk(num, n0, n1);
    unpk(den, d0, d1);
    float2 o;
    o.x = __fdividef(n0, d0);
    o.y = __fdividef(n1, d1);
    *(float2*)&out[pbase + (by + ty) * W + bx + col] = o;
}

extern "C" void kernel_launch(void* const* d_in, const int* in_sizes, int n_in,
                              void* d_out, int out_size) {
    const float* x = (const float*)d_in[0];
    float* y = (float*)d_out;
    dim3 block(BLK_X, BLK_Y);
    dim3 grid(W / TILE_W, H / TILE_H, NPLANES);
    bilateral_kernel<<<grid, block>>>(x, y);
}

// round 4
// speedup vs baseline: 1.1783x; 1.0821x over previous
#include <cuda_runtime.h>

// Bilateral 5x5, sigma_color = sigma_space = 1.1, reflect pad, (16,3,512,512) f32.
//
// out = sum_k exp(-d^2*a)*g_k*p_k / sum_k exp(-d^2*a)*g_k   (a = 1/(2*1.1^2));
// both reference normalizations cancel. exp(-a*u), u in [0,1], approximated by
// a deg-2 Chebyshev poly (abs err ~3e-4 -> end-to-end ~5e-5).
//
// R4: per-spatial-class accumulators (5 classes, center exact) remove the
// per-tap g-mul and row combines; deg-2 poly; f32x2 sub. ~154 f2 ops/thread
// (2 px/thread) vs ~209 in R3.

#define H 512
#define W 512
#define NPLANES 48

#define TILE_W 64
#define TILE_H 8
#define BLK_X 32
#define BLK_Y 8
#define SM_W  68
#define SM_H  12
#define SM_N  (SM_H * SM_W)

// spatial class weights (products of 1D gaussian exp(-a*d^2), d in {0,1,2})
#define S1 0.66151464f   // G0*G1
#define S2 0.19149516f   // G0*G2
#define S3 0.43760162f   // G1*G1
#define S4 0.12667664f   // G1*G2
#define S5 0.03670410f   // G2*G2

// deg-2 Chebyshev coeffs for exp(-a*u), u in [0,1]
#define Q0  0.99969391f
#define Q1 -0.40757903f
#define Q2  0.06969310f

typedef unsigned long long u64;

__device__ __forceinline__ u64 pk(float lo, float hi) {
    u64 r; asm("mov.b64 %0, {%1, %2};" : "=l"(r) : "f"(lo), "f"(hi)); return r;
}
__device__ __forceinline__ u64 f2add(u64 a, u64 b) {
    u64 d; asm("add.rn.f32x2 %0, %1, %2;" : "=l"(d) : "l"(a), "l"(b)); return d;
}
__device__ __forceinline__ u64 f2sub(u64 a, u64 b) {
    u64 d; asm("sub.rn.f32x2 %0, %1, %2;" : "=l"(d) : "l"(a), "l"(b)); return d;
}
__device__ __forceinline__ u64 f2mul(u64 a, u64 b) {
    u64 d; asm("mul.rn.f32x2 %0, %1, %2;" : "=l"(d) : "l"(a), "l"(b)); return d;
}
__device__ __forceinline__ u64 f2fma(u64 a, u64 b, u64 c) {
    u64 d; asm("fma.rn.f32x2 %0, %1, %2, %3;" : "=l"(d) : "l"(a), "l"(b), "l"(c)); return d;
}
__device__ __forceinline__ void unpk(u64 q, float& lo, float& hi) {
    asm("mov.b64 {%0, %1}, %2;" : "=f"(lo), "=f"(hi) : "l"(q));
}

__device__ __forceinline__ int reflect_idx(int i, int n) {
    if (i < 0)  i = -i;
    if (i >= n) i = 2 * n - 2 - i;
    return i;
}

__global__ __launch_bounds__(BLK_X * BLK_Y, 5)
void bilateral_kernel(const float* __restrict__ in, float* __restrict__ out) {
    // smB[r][c] == smA[r][c+1]  (shifted copy -> odd pairs are 8B-aligned)
    __shared__ __align__(8) float smA[SM_H][SM_W];
    __shared__ __align__(8) float smB[SM_H][SM_W];

    const int tx = threadIdx.x;
    const int ty = threadIdx.y;
    const int bx = blockIdx.x * TILE_W;
    const int by = blockIdx.y * TILE_H;
    const long pbase = (long)blockIdx.z * (H * W);

    const int t = ty * BLK_X + tx;
    #pragma unroll
    for (int idx = 0; idx < SM_N; idx += BLK_X * BLK_Y) {
        int i = idx + t;
        if (i < SM_N) {
            int r = i / SM_W;
            int c = i - r * SM_W;
            int gy = reflect_idx(by - 2 + r, H);
            int gx = reflect_idx(bx - 2 + c, W);
            float v = in[pbase + gy * W + gx];
            smA[r][c] = v;
            if (c > 0) smB[r][c - 1] = v;
        }
    }
    __syncthreads();

    const u64 Q2p = pk(Q2, Q2);
    const u64 Q1p = pk(Q1, Q1);
    const u64 Q0p = pk(Q0, Q0);

    const int col = 2 * tx;
    const u64 ctr = *(const u64*)&smA[ty + 2][col + 2];

    // class accumulators (center excluded; its w==1 exactly -> init totals)
    u64 n1 = 0ull, n2 = 0ull, n3 = 0ull, n4 = 0ull, n5 = 0ull;
    u64 d1 = 0ull, d2 = 0ull, d3 = 0ull, d4 = 0ull, d5 = 0ull;

    #define TAP(P, NA, DA)                                  \
    {                                                       \
        u64 dd = f2sub((P), ctr);                           \
        u64 uu = f2mul(dd, dd);                             \
        u64 tt = f2fma(Q2p, uu, Q1p);                       \
        u64 ww = f2fma(tt, uu, Q0p);                        \
        DA = f2add(DA, ww);                                 \
        NA = f2fma(ww, (P), NA);                            \
    }

    #define ROWLOAD(ki)                                     \
        const float* rA = &smA[ty + (ki)][col];             \
        const float* rB = &smB[ty + (ki)][col];             \
        u64 p0 = *(const u64*)(rA + 0);                     \
        u64 p1 = *(const u64*)(rB + 0);                     \
        u64 p2 = *(const u64*)(rA + 2);                     \
        u64 p3 = *(const u64*)(rB + 2);                     \
        u64 p4 = *(const u64*)(rA + 4);

    {   // ki = 0  (|oy|=2): c5 c4 c2 c4 c5
        ROWLOAD(0)
        TAP(p0, n5, d5) TAP(p1, n4, d4) TAP(p2, n2, d2) TAP(p3, n4, d4) TAP(p4, n5, d5)
    }
    {   // ki = 1  (|oy|=1): c4 c3 c1 c3 c4
        ROWLOAD(1)
        TAP(p0, n4, d4) TAP(p1, n3, d3) TAP(p2, n1, d1) TAP(p3, n3, d3) TAP(p4, n4, d4)
    }
    {   // ki = 2  (oy=0): c2 c1 [center] c1 c2
        ROWLOAD(2)
        TAP(p0, n2, d2) TAP(p1, n1, d1) TAP(p3, n1, d1) TAP(p4, n2, d2)
        (void)p2;
    }
    {   // ki = 3
        ROWLOAD(3)
        TAP(p0, n4, d4) TAP(p1, n3, d3) TAP(p2, n1, d1) TAP(p3, n3, d3) TAP(p4, n4, d4)
    }
    {   // ki = 4
        ROWLOAD(4)
        TAP(p0, n5, d5) TAP(p1, n4, d4) TAP(p2, n2, d2) TAP(p3, n4, d4) TAP(p4, n5, d5)
    }
    #undef TAP
    #undef ROWLOAD

    // totals: center contributes w=1 (exact), s=1
    u64 numq = ctr;
    u64 denq = pk(1.0f, 1.0f);
    numq = f2fma(pk(S1, S1), n1, numq);
    denq = f2fma(pk(S1, S1), d1, denq);
    numq = f2fma(pk(S2, S2), n2, numq);
    denq = f2fma(pk(S2, S2), d2, denq);
    numq = f2fma(pk(S3, S3), n3, numq);
    denq = f2fma(pk(S3, S3), d3, denq);
    numq = f2fma(pk(S4, S4), n4, numq);
    denq = f2fma(pk(S4, S4), d4, denq);
    numq = f2fma(pk(S5, S5), n5, numq);
    denq = f2fma(pk(S5, S5), d5, denq);

    float a0, a1, b0, b1;
    unpk(numq, a0, a1);
    unpk(denq, b0, b1);
    float2 o;
    o.x = __fdividef(a0, b0);
    o.y = __fdividef(a1, b1);
    *(float2*)&out[pbase + (by + ty) * W + bx + col] = o;
}

extern "C" void kernel_launch(void* const* d_in, const int* in_sizes, int n_in,
                              void* d_out, int out_size) {
    const float* x = (const float*)d_in[0];
    float* y = (float*)d_out;
    dim3 block(BLK_X, BLK_Y);
    dim3 grid(W / TILE_W, H / TILE_H, NPLANES);
    bilateral_kernel<<<grid, block>>>(x, y);
}